// round 10
// baseline (speedup 1.0000x reference)
#include <cuda_runtime.h>
#include <math.h>
#include <stdint.h>

#define NTOK 8192
#define DDIM 1024
#define FDIM 2816
#define NEXP 8
#define CAP  8192

// ---------------- device scratch (referenced ONLY from device code) ----------------
__device__ int   g_count[NEXP];
__device__ int   g_tok[NEXP * CAP];
__device__ float g_swt[NEXP * CAP];                     // combine weight per slot
__device__ float g_xr[(size_t)NTOK * DDIM];
__device__ float g_wgr[(size_t)NEXP * DDIM * FDIM];
__device__ float g_wur[(size_t)NEXP * DDIM * FDIM];
__device__ float g_wdr[(size_t)NEXP * FDIM * DDIM];
__device__ float g_act[(size_t)NEXP * CAP * FDIM];

// ---------------- helpers ----------------
__device__ __forceinline__ float rn_tf32(float x) {
    float r; asm("cvt.rna.tf32.f32 %0, %1;" : "=f"(r) : "f"(x)); return r;
}
__device__ __forceinline__ uint32_t smem_u32(const void* p) {
    uint32_t a;
    asm("{ .reg .u64 t; cvta.to.shared.u64 t, %1; cvt.u32.u64 %0, t; }" : "=r"(a) : "l"(p));
    return a;
}

#define CPA(dst, src, n) asm volatile("cp.async.cg.shared.global [%0], [%1], 16, %2;" :: "r"(dst), "l"(src), "r"(n) : "memory")
#define CPA_COMMIT()     asm volatile("cp.async.commit_group;" ::: "memory")
#define CPA_WAIT0()      asm volatile("cp.async.wait_group 0;" ::: "memory")

#define MMA_TF32(d, a, b) \
    asm volatile("mma.sync.aligned.m16n8k8.row.col.f32.tf32.tf32.f32 " \
        "{%0,%1,%2,%3}, {%4,%5,%6,%7}, {%8,%9}, {%0,%1,%2,%3};" \
        : "+f"((d)[0]), "+f"((d)[1]), "+f"((d)[2]), "+f"((d)[3]) \
        : "r"((a)[0]), "r"((a)[1]), "r"((a)[2]), "r"((a)[3]), "r"((b)[0]), "r"((b)[1]))

// ---------------- kernel 0: reset ----------------
__global__ void reset_kernel() {
    if (threadIdx.x < NEXP) g_count[threadIdx.x] = 0;
}

// ---------------- kernel 0b: zero output (harness poisons it) ----------------
__global__ void zero_out_kernel(float* __restrict__ out) {
    size_t i = (size_t)blockIdx.x * 256 + threadIdx.x;
    ((float4*)out)[i] = make_float4(0.f, 0.f, 0.f, 0.f);
}

// ---------------- kernel 1: router ----------------
__global__ void router_kernel(const float* __restrict__ X, const float* __restrict__ RW) {
    __shared__ float sW[NEXP * DDIM];
    const int tid = threadIdx.x;
    for (int i = tid; i < NEXP * DDIM; i += 128) {
        int d = i >> 3, e = i & 7;
        sW[e * DDIM + d] = RW[i];
    }
    __syncthreads();
    const int warp = tid >> 5, lane = tid & 31;
    const int t = blockIdx.x * 4 + warp;
    const float* xr = X + (size_t)t * DDIM;
    float acc[NEXP];
#pragma unroll
    for (int e = 0; e < NEXP; e++) acc[e] = 0.f;
    for (int d = lane; d < DDIM; d += 32) {
        float xv = xr[d];
#pragma unroll
        for (int e = 0; e < NEXP; e++) acc[e] += xv * sW[e * DDIM + d];
    }
#pragma unroll
    for (int e = 0; e < NEXP; e++)
#pragma unroll
        for (int off = 16; off > 0; off >>= 1)
            acc[e] += __shfl_xor_sync(0xFFFFFFFFu, acc[e], off);
    if (lane == 0) {
        int i0 = 0; float s0 = acc[0];
#pragma unroll
        for (int e = 1; e < NEXP; e++) if (acc[e] > s0) { s0 = acc[e]; i0 = e; }
        int i1 = -1; float s1 = -INFINITY;
#pragma unroll
        for (int e = 0; e < NEXP; e++) if (e != i0 && acc[e] > s1) { s1 = acc[e]; i1 = e; }
        float w0 = 1.f / (1.f + expf(s1 - s0));
        float w1 = 1.f - w0;
        int p0 = atomicAdd(&g_count[i0], 1);
        int p1 = atomicAdd(&g_count[i1], 1);
        g_tok[i0 * CAP + p0] = t;   g_swt[i0 * CAP + p0] = w0;
        g_tok[i1 * CAP + p1] = t;   g_swt[i1 * CAP + p1] = w1;
    }
}

// ---------------- kernel 1b/1c: round to tf32 ----------------
__global__ void roundx_kernel(const float* __restrict__ X) {
    size_t i = (size_t)blockIdx.x * 256 + threadIdx.x;
    float4 v = ((const float4*)X)[i];
    v.x = rn_tf32(v.x); v.y = rn_tf32(v.y); v.z = rn_tf32(v.z); v.w = rn_tf32(v.w);
    ((float4*)g_xr)[i] = v;
}
__global__ void roundw_kernel(const float* __restrict__ Wg,
                              const float* __restrict__ Wu,
                              const float* __restrict__ Wd) {
    size_t i = (size_t)blockIdx.x * 256 + threadIdx.x;
    float4 a = ((const float4*)Wg)[i];
    a.x = rn_tf32(a.x); a.y = rn_tf32(a.y); a.z = rn_tf32(a.z); a.w = rn_tf32(a.w);
    ((float4*)g_wgr)[i] = a;
    float4 b = ((const float4*)Wu)[i];
    b.x = rn_tf32(b.x); b.y = rn_tf32(b.y); b.z = rn_tf32(b.z); b.w = rn_tf32(b.w);
    ((float4*)g_wur)[i] = b;
    float4 c = ((const float4*)Wd)[i];
    c.x = rn_tf32(c.x); c.y = rn_tf32(c.y); c.z = rn_tf32(c.z); c.w = rn_tf32(c.w);
    ((float4*)g_wdr)[i] = c;
}

// ================= tf32 mma.sync GEMMs =================
// A smem [m][k] rows of 128B, chunk swizzle c^=(r&7).
// B smem [k][n] rows of 512B/1024B, chunk swizzle c^=2*(k&3).

__device__ __forceinline__ void load_frag_a2(
    const float* A, int k8, int wm, int lr, int lc, uint32_t fa[2][4]) {
#pragma unroll
    for (int mi = 0; mi < 2; mi++) {
        const int r0 = wm * 32 + mi * 16 + lr;
#pragma unroll
        for (int h = 0; h < 2; h++) {
            const int cx = (((2 * k8 + h) ^ lr) << 2) + lc;
            fa[mi][h * 2 + 0] = __float_as_uint(A[r0 * 32 + cx]);
            fa[mi][h * 2 + 1] = __float_as_uint(A[(r0 + 8) * 32 + cx]);
        }
    }
}
__device__ __forceinline__ void load_frag_b4(
    const float* B, int k8, int wn, int lr, int lc, uint32_t fb[4][2]) {
#pragma unroll
    for (int ni = 0; ni < 4; ni++) {
        const int c = wn * 8 + ni * 2 + (lr >> 2);
        const int bx = ((c ^ (lc << 1)) << 2) + (lr & 3);
#pragma unroll
        for (int h = 0; h < 2; h++)
            fb[ni][h] = __float_as_uint(B[(k8 * 8 + lc + 4 * h) * 128 + bx]);
    }
}
__device__ __forceinline__ void load_frag_b8w(
    const float* B, int k8, int wn, int lr, int lc, uint32_t fb[8][2]) {
#pragma unroll
    for (int ni = 0; ni < 8; ni++) {
        const int c = wn * 16 + ni * 2 + (lr >> 2);
        const int bx = ((c ^ (lc << 1)) << 2) + (lr & 3);
#pragma unroll
        for (int h = 0; h < 2; h++)
            fb[ni][h] = __float_as_uint(B[(k8 * 8 + lc + 4 * h) * 256 + bx]);
    }
}

// ---------------- kernel 2: fused gate+up + SiLU (CTA 64x128, 2-stage, 80KB, 2 CTA/SM) ----------------
__global__ void __launch_bounds__(256, 2)
gateup_mma_kernel() {
    extern __shared__ float smem[];
    float* As  = smem;              // 2 stages x 2048 floats
    float* Bgs = smem + 4096;       // 2 stages x 4096
    float* Bus = smem + 12288;      // 2 stages x 4096

    const int e = blockIdx.z;
    const int cnt = g_count[e];
    const int m0 = blockIdx.x * 64;
    if (m0 >= cnt) return;
    const int n0 = blockIdx.y * 128;

    const int tid = threadIdx.x, wid = tid >> 5, lane = tid & 31;
    const int wm = wid & 1, wn = wid >> 1;
    const int lr = lane >> 2, lc = lane & 3;

    const int ar = tid >> 2;
    const bool av = (m0 + ar) < cnt;
    const float* arow = g_xr + (size_t)(av ? g_tok[e * CAP + m0 + ar] : 0) * DDIM;
    const int an = av ? 16 : 0;
    uint32_t aoff[2]; int ac[2];
#pragma unroll
    for (int i = 0; i < 2; i++) {
        int c = (tid & 3) + 4 * i;
        ac[i] = c;
        aoff[i] = (uint32_t)(ar * 128 + ((c ^ (ar & 7)) << 4));
    }
    const int bk = tid >> 3;
    const float* grow = g_wgr + ((size_t)e * DDIM + bk) * FDIM + n0;
    const float* urow = g_wur + ((size_t)e * DDIM + bk) * FDIM + n0;
    uint32_t boff[4]; int bc[4];
#pragma unroll
    for (int i = 0; i < 4; i++) {
        int c = (tid & 7) + 8 * i;
        bc[i] = c;
        boff[i] = (uint32_t)(bk * 512 + ((c ^ ((bk & 3) << 1)) << 4));
    }

    const uint32_t sA = smem_u32(As), sG = smem_u32(Bgs), sU = smem_u32(Bus);

    float accg[2][4][4], accu[2][4][4];
#pragma unroll
    for (int mi = 0; mi < 2; mi++)
#pragma unroll
        for (int ni = 0; ni < 4; ni++)
#pragma unroll
            for (int q = 0; q < 4; q++) { accg[mi][ni][q] = 0.f; accu[mi][ni][q] = 0.f; }

    const int KT = DDIM / 32;   // 32

#define GU_PREFETCH(s) do { \
    int _buf = (s) & 1; \
    uint32_t _da = sA + _buf * 8192, _dg = sG + _buf * 16384, _du = sU + _buf * 16384; \
    const float* _ap = arow + (s) * 32; \
    const float* _gp = grow + (size_t)(s) * 32 * FDIM; \
    const float* _up = urow + (size_t)(s) * 32 * FDIM; \
    _Pragma("unroll") \
    for (int _i = 0; _i < 2; _i++) CPA(_da + aoff[_i], _ap + ac[_i] * 4, an); \
    _Pragma("unroll") \
    for (int _i = 0; _i < 4; _i++) { \
        CPA(_dg + boff[_i], _gp + bc[_i] * 4, 16); \
        CPA(_du + boff[_i], _up + bc[_i] * 4, 16); \
    } } while (0)

    GU_PREFETCH(0); CPA_COMMIT();

    for (int s = 0; s < KT; s++) {
        CPA_WAIT0();
        __syncthreads();
        if (s + 1 < KT) { GU_PREFETCH(s + 1); }
        CPA_COMMIT();
        const int buf = s & 1;
        const float* A = As  + buf * 2048;
        const float* G = Bgs + buf * 4096;
        const float* U = Bus + buf * 4096;
        uint32_t fa[2][2][4], fg[2][4][2], fu[2][4][2];
        load_frag_a2(A, 0, wm, lr, lc, fa[0]);
        load_frag_b4(G, 0, wn, lr, lc, fg[0]);
        load_frag_b4(U, 0, wn, lr, lc, fu[0]);
#pragma unroll
        for (int k8 = 0; k8 < 4; k8++) {
            const int cur = k8 & 1, nxt = (k8 + 1) & 1;
            if (k8 < 3) {
                load_frag_a2(A, k8 + 1, wm, lr, lc, fa[nxt]);
                load_frag_b4(G, k8 + 1, wn, lr, lc, fg[nxt]);
                load_frag_b4(U, k8 + 1, wn, lr, lc, fu[nxt]);
            }
#pragma unroll
            for (int ni = 0; ni < 4; ni++)
#pragma unroll
                for (int mi = 0; mi < 2; mi++) {
                    MMA_TF32(accg[mi][ni], fa[cur][mi], fg[cur][ni]);
                    MMA_TF32(accu[mi][ni], fa[cur][mi], fu[cur][ni]);
                }
        }
    }

    // epilogue: act = rn_tf32(silu(g)*u)
#pragma unroll
    for (int mi = 0; mi < 2; mi++) {
        const int r = wm * 32 + mi * 16 + lr;
        const size_t row0 = (size_t)e * CAP + m0 + r;
#pragma unroll
        for (int ni = 0; ni < 4; ni++) {
            const int col = n0 + wn * 32 + ni * 8 + 2 * lc;
            if (m0 + r < cnt) {
                float g0 = accg[mi][ni][0], g1 = accg[mi][ni][1];
                float2 v;
                v.x = rn_tf32((g0 / (1.f + __expf(-g0))) * accu[mi][ni][0]);
                v.y = rn_tf32((g1 / (1.f + __expf(-g1))) * accu[mi][ni][1]);
                *(float2*)&g_act[row0 * FDIM + col] = v;
            }
            if (m0 + r + 8 < cnt) {
                float g2 = accg[mi][ni][2], g3 = accg[mi][ni][3];
                float2 v;
                v.x = rn_tf32((g2 / (1.f + __expf(-g2))) * accu[mi][ni][2]);
                v.y = rn_tf32((g3 / (1.f + __expf(-g3))) * accu[mi][ni][3]);
                *(float2*)&g_act[(row0 + 8) * FDIM + col] = v;
            }
        }
    }
}

// ---------------- kernel 3: down GEMM + fused weighted atomic combine ----------------
// CTA 64x256x32, warp 32x64, 2-stage, 80KB, 2 CTA/SM.
__global__ void __launch_bounds__(256, 2)
down_mma_kernel(float* __restrict__ out) {
    extern __shared__ float smem[];
    float* As = smem;               // 2 stages x 2048 floats
    float* Bs = smem + 4096;        // 2 stages x 8192 floats

    const int e = blockIdx.z;
    const int cnt = g_count[e];
    const int m0 = blockIdx.x * 64;
    if (m0 >= cnt) return;
    const int n0 = blockIdx.y * 256;

    const int tid = threadIdx.x, wid = tid >> 5, lane = tid & 31;
    const int wm = wid & 1, wn = wid >> 1;
    const int lr = lane >> 2, lc = lane & 3;

    const int ar = tid >> 2;
    const bool av = (m0 + ar) < cnt;
    const float* arow = g_act + ((size_t)e * CAP + m0 + (av ? ar : 0)) * FDIM;
    const int an = av ? 16 : 0;
    uint32_t aoff[2]; int ac[2];
#pragma unroll
    for (int i = 0; i < 2; i++) {
        int c = (tid & 3) + 4 * i;
        ac[i] = c;
        aoff[i] = (uint32_t)(ar * 128 + ((c ^ (ar & 7)) << 4));
    }
    const int bk = tid >> 3;
    const float* brow = g_wdr + ((size_t)e * FDIM + bk) * DDIM + n0;
    uint32_t boff[8]; int bc[8];
#pragma unroll
    for (int i = 0; i < 8; i++) {
        int c = (tid & 7) + 8 * i;
        bc[i] = c;
        boff[i] = (uint32_t)(bk * 1024 + ((c ^ ((bk & 3) << 1)) << 4));
    }

    const uint32_t sA = smem_u32(As), sB = smem_u32(Bs);

    float acc[2][8][4];
#pragma unroll
    for (int mi = 0; mi < 2; mi++)
#pragma unroll
        for (int ni = 0; ni < 8; ni++)
#pragma unroll
            for (int q = 0; q < 4; q++) acc[mi][ni][q] = 0.f;

    const int KT = FDIM / 32;   // 88

#define DN_PREFETCH(s) do { \
    int _buf = (s) & 1; \
    uint32_t _da = sA + _buf * 8192, _db = sB + _buf * 32768; \
    const float* _ap = arow + (s) * 32; \
    const float* _bp = brow + (size_t)(s) * 32 * DDIM; \
    _Pragma("unroll") \
    for (int _i = 0; _i < 2; _i++) CPA(_da + aoff[_i], _ap + ac[_i] * 4, an); \
    _Pragma("unroll") \
    for (int _i = 0; _i < 8; _i++) CPA(_db + boff[_i], _bp + bc[_i] * 4, 16); \
    } while (0)

    DN_PREFETCH(0); CPA_COMMIT();

    for (int s = 0; s < KT; s++) {
        CPA_WAIT0();
        __syncthreads();
        if (s + 1 < KT) { DN_PREFETCH(s + 1); }
        CPA_COMMIT();
        const int buf = s & 1;
        const float* A = As + buf * 2048;
        const float* B = Bs + buf * 8192;
        uint32_t fa[2][2][4];
        load_frag_a2(A, 0, wm, lr, lc, fa[0]);
#pragma unroll
        for (int k8 = 0; k8 < 4; k8++) {
            const int cur = k8 & 1, nxt = (k8 + 1) & 1;
            uint32_t fb[8][2];
            load_frag_b8w(B, k8, wn, lr, lc, fb);
            if (k8 < 3) load_frag_a2(A, k8 + 1, wm, lr, lc, fa[nxt]);
#pragma unroll
            for (int ni = 0; ni < 8; ni++)
#pragma unroll
                for (int mi = 0; mi < 2; mi++)
                    MMA_TF32(acc[mi][ni], fa[cur][mi], fb[ni]);
        }
    }

    // epilogue: out[tok] += w * acc (exactly 2 contributions per token -> deterministic)
#pragma unroll
    for (int mi = 0; mi < 2; mi++) {
        const int r = wm * 32 + mi * 16 + lr;
        const int slot0 = e * CAP + m0 + r;
#pragma unroll
        for (int half = 0; half < 2; half++) {
            const int rr = r + half * 8;
            const int slot = slot0 + half * 8;
            if (m0 + rr < cnt) {
                const float w = g_swt[slot];
                float* orow = out + (size_t)g_tok[slot] * DDIM;
#pragma unroll
                for (int ni = 0; ni < 8; ni++) {
                    const int col = n0 + wn * 64 + ni * 8 + 2 * lc;
                    atomicAdd(&orow[col],     w * acc[mi][ni][2 * half + 0]);
                    atomicAdd(&orow[col + 1], w * acc[mi][ni][2 * half + 1]);
                }
            }
        }
    }
}

// ---------------- launch ----------------
extern "C" void kernel_launch(void* const* d_in, const int* in_sizes, int n_in,
                              void* d_out, int out_size) {
    const float* x  = (const float*)d_in[0];
    const float* rw = (const float*)d_in[1];
    const float* wg = (const float*)d_in[2];
    const float* wu = (const float*)d_in[3];
    const float* wd = (const float*)d_in[4];
    float* out = (float*)d_out;

    cudaFuncSetAttribute(gateup_mma_kernel, cudaFuncAttributeMaxDynamicSharedMemorySize, 81920);
    cudaFuncSetAttribute(down_mma_kernel,   cudaFuncAttributeMaxDynamicSharedMemorySize, 81920);

    reset_kernel<<<1, 32>>>();
    zero_out_kernel<<<(NTOK * DDIM / 4) / 256, 256>>>(out);
    router_kernel<<<NTOK / 4, 128>>>(x, rw);

    roundx_kernel<<<(NTOK * DDIM / 4) / 256, 256>>>(x);
    roundw_kernel<<<(NEXP * DDIM * FDIM / 4) / 256, 256>>>(wg, wu, wd);

    gateup_mma_kernel<<<dim3(CAP / 64, FDIM / 128, NEXP), 256, 81920>>>();
    down_mma_kernel<<<dim3(CAP / 64, DDIM / 256, NEXP), 256, 81920>>>(out);
}